// round 7
// baseline (speedup 1.0000x reference)
#include <cuda_runtime.h>
#include <cstddef>
#include <cstdint>

// Problem constants
#define NB   256            // batch
#define NU   8              // in_units
#define NI   1152           // in_size
#define NJ   10             // out_units
#define ND   16             // out_size
#define NJD  (NJ*ND)        // 160
#define NK   (NU*NI)        // 9216
#define NM   (NJD*NU)       // 1280

// Packed fp32x2 helpers (Blackwell sm_103a)
#define FMA_F32X2(acc, a, b) \
    asm("fma.rn.f32x2 %0, %1, %2, %0;" : "+l"(acc) : "l"(a), "l"(b))
#define UNPACK2(lo, hi, in) \
    asm("mov.b64 {%0, %1}, %2;" : "=r"(lo), "=r"(hi) : "l"(in))

// Scratch (device globals; allocation-free per harness rules)
__device__ float g_WT[(size_t)NJD * NU * NI];   // [jd][u][i]  5.9 MB
__device__ float g_G [(size_t)NJD * NU * NI];   // [jd][u][i]  5.9 MB
__device__ float g_s [NB * NJD];
__device__ float g_v [NB * NJD];
__device__ float g_b [NI * NJ];
__device__ float g_cT[NJ * NI];                 // coupling coeffs [j][i]
__device__ float g_uv[NI * NJ];                 // written non-atomically by uv_reduce

// ---------------------------------------------------------------------------
// Kernel 0 (once): WT[m][i] = W[i][m]
// ---------------------------------------------------------------------------
__global__ void prep_kernel(const float* __restrict__ W) {
    __shared__ float t[32][33];
    const int i0 = blockIdx.x * 32, m0 = blockIdx.y * 32;
    const int tx = threadIdx.x, ty = threadIdx.y;
#pragma unroll
    for (int r = 0; r < 4; r++) {
        int i = i0 + ty + 8 * r;
        t[ty + 8 * r][tx] = W[(size_t)i * NM + m0 + tx];
    }
    __syncthreads();
#pragma unroll
    for (int r = 0; r < 4; r++) {
        int m = m0 + ty + 8 * r;
        g_WT[(size_t)m * NI + i0 + tx] = t[tx][ty + 8 * r];
    }
}

// ---------------------------------------------------------------------------
// Kernel 1: routing softmax over i (per j), fused b-update; zeroes g_s.
// (round-4 proven version)
// ---------------------------------------------------------------------------
__global__ void softmax_kernel(int init) {
    const int j = blockIdx.x;
    const int t = threadIdx.x;
    __shared__ float sb[NI];
    __shared__ float red[128];

    float mx = -1e30f;
    for (int i = t; i < NI; i += 128) {
        float bn = init ? 1.0f
                        : (g_b[i * NJ + j] + g_uv[i * NJ + j] * (1.0f / (float)NB));
        g_b[i * NJ + j] = bn;
        sb[i] = bn;
        mx = fmaxf(mx, bn);
    }
    red[t] = mx;
    __syncthreads();
    for (int s = 64; s > 0; s >>= 1) {
        if (t < s) red[t] = fmaxf(red[t], red[t + s]);
        __syncthreads();
    }
    mx = red[0];
    __syncthreads();

    float sum = 0.f;
    for (int i = t; i < NI; i += 128) {
        float e = expf(sb[i] - mx);
        sb[i] = e;
        sum += e;
    }
    red[t] = sum;
    __syncthreads();
    for (int s = 64; s > 0; s >>= 1) {
        if (t < s) red[t] += red[t + s];
        __syncthreads();
    }
    const float inv = 1.0f / red[0];
    __syncthreads();
    for (int i = t; i < NI; i += 128) g_cT[j * NI + i] = sb[i] * inv;

    for (int k = t; k < (NB * NJD) / NJ; k += 128)
        g_s[j * ((NB * NJD) / NJ) + k] = 0.0f;
}

// ---------------------------------------------------------------------------
// Kernel 2: s[b,jd] += sum_k x[b,k] * cT[j,i(k)] * WT[jd,k]
// M=256(b) x N=160(jd) x K=9216, split-K x36 (chunk 256).
// grid (4 jd-tiles, 36 ksplit), block 256. CTA 256b x 40jd; thread 8b x 5jd.
// Warp layout: tx=t&7 (jd), ty=t>>3 (b). Within a warp ty spans only 4 values
// -> A LDS.128s are 8-lane broadcast groups (~1 phase); B is duplicated pairs
// (8 distinct LDS.64 = 1 phase). 7 crossbar phases per 20 FFMA2.
// ---------------------------------------------------------------------------
__global__ __launch_bounds__(256) void s_gemm(const float* __restrict__ x) {
    __shared__ float As[2][16][260];   // [k][b], pitch 260 (16B-aligned rows)
    __shared__ float Bs[2][16][82];    // [k][2*jd_local] duplicated pairs

    const int t   = threadIdx.x;
    const int tx  = t & 7;             // 8 jd-groups of 5
    const int ty  = t >> 3;            // 32 b-groups of 8
    const int jd0 = blockIdx.x * 40;
    const int k0  = blockIdx.y * 256;

    unsigned long long acc2[4][5];
#pragma unroll
    for (int p = 0; p < 4; p++)
#pragma unroll
        for (int q = 0; q < 5; q++) acc2[p][q] = 0ULL;

    float4 af[4];
    float  bf[3];

    auto fetch = [&](int kb) {
        const int kbase = k0 + kb * 16;
#pragma unroll
        for (int r = 0; r < 4; r++) {
            int idx4 = t + 256 * r;                   // 1024 float4 = 256b x 4k4
            int bl = idx4 >> 2, k4 = idx4 & 3;
            af[r] = *(const float4*)&x[(size_t)bl * NK + kbase + k4 * 4];
        }
#pragma unroll
        for (int r = 0; r < 3; r++) {
            int idx = t + 256 * r;                    // 640 = 16k x 40jd
            if (idx < 640) {
                int kk = idx & 15, col = idx >> 4;
                int kg = kbase + kk;
                int u  = kg / NI;
                int i  = kg - u * NI;
                int jd = jd0 + col;
                bf[r] = g_WT[(size_t)jd * NK + kg] * g_cT[(jd >> 4) * NI + i];
            }
        }
    };
    auto sts = [&](int buf) {
#pragma unroll
        for (int r = 0; r < 4; r++) {
            int idx4 = t + 256 * r;
            int bl = idx4 >> 2, k4 = idx4 & 3;
            As[buf][k4 * 4 + 0][bl] = af[r].x;
            As[buf][k4 * 4 + 1][bl] = af[r].y;
            As[buf][k4 * 4 + 2][bl] = af[r].z;
            As[buf][k4 * 4 + 3][bl] = af[r].w;
        }
#pragma unroll
        for (int r = 0; r < 3; r++) {
            int idx = t + 256 * r;
            if (idx < 640) {
                int kk = idx & 15, col = idx >> 4;
                *(float2*)&Bs[buf][kk][col * 2] = make_float2(bf[r], bf[r]);
            }
        }
    };

    fetch(0);
    sts(0);
    __syncthreads();

    for (int kb = 0; kb < 16; kb++) {
        const int buf = kb & 1;
        if (kb < 15) fetch(kb + 1);
#pragma unroll
        for (int kk = 0; kk < 16; kk++) {
            const float* arow = &As[buf][kk][ty * 8];
            ulonglong2 a01 = *(const ulonglong2*)arow;
            ulonglong2 a23 = *(const ulonglong2*)(arow + 4);
#pragma unroll
            for (int q = 0; q < 5; q++) {
                unsigned long long bb =
                    *(const unsigned long long*)&Bs[buf][kk][(tx * 5 + q) * 2];
                FMA_F32X2(acc2[0][q], a01.x, bb);
                FMA_F32X2(acc2[1][q], a01.y, bb);
                FMA_F32X2(acc2[2][q], a23.x, bb);
                FMA_F32X2(acc2[3][q], a23.y, bb);
            }
        }
        if (kb < 15) {
            sts(buf ^ 1);
            __syncthreads();
        }
    }

#pragma unroll
    for (int p = 0; p < 4; p++)
#pragma unroll
        for (int q = 0; q < 5; q++) {
            unsigned lo, hi;
            UNPACK2(lo, hi, acc2[p][q]);
            int jd = jd0 + tx * 5 + q;
            int b  = ty * 8 + 2 * p;
            atomicAdd(&g_s[b * NJD + jd], __uint_as_float(lo));
            atomicAdd(&g_s[(b + 1) * NJD + jd], __uint_as_float(hi));
        }
}

// ---------------------------------------------------------------------------
// Kernel 3: squash. msq[b,d] = sum_j s[b,j,d]^2 ; v = s * sqrt(msq)/(1+msq)
// ---------------------------------------------------------------------------
__global__ void squash_kernel(float* __restrict__ dst) {
    const int t = blockIdx.x * blockDim.x + threadIdx.x;
    if (t >= NB * ND) return;
    const int b = t >> 4, d = t & 15;
    float* v = dst ? dst : g_v;

    const float* sp = g_s + b * NJD + d;
    float vals[NJ];
    float msq = 0.f;
#pragma unroll
    for (int j = 0; j < NJ; j++) {
        vals[j] = sp[j * ND];
        msq = fmaf(vals[j], vals[j], msq);
    }
    const float scale = sqrtf(msq) / (1.0f + msq);
#pragma unroll
    for (int j = 0; j < NJ; j++) v[b * NJD + j * ND + d] = vals[j] * scale;
}

// ---------------------------------------------------------------------------
// Kernel 4: G[m, n] = sum_b v[b,m] * x[b,n]    (m=jd, n=(u,i))
// M=160 x N=9216 x K=256. grid (36 n-tiles, 4 m-tiles), block 256.
// CTA 40m x 256n; thread 5m x 8n. Same broadcast-friendly warp layout as
// s_gemm: tx=t&7 (m), ty=t>>3 (n). V duplicated pairs.
// ---------------------------------------------------------------------------
__global__ __launch_bounds__(256) void g_gemm(const float* __restrict__ x) {
    __shared__ float Xs[2][16][260];   // [k][n_local]
    __shared__ float Vs[2][16][82];    // [k][2*m_local] duplicated

    const int t  = threadIdx.x;
    const int tx = t & 7;              // 8 m-groups of 5
    const int ty = t >> 3;             // 32 n-groups of 8
    const int n0 = blockIdx.x * 256;
    const int m0 = blockIdx.y * 40;

    unsigned long long acc2[4][5];
#pragma unroll
    for (int p = 0; p < 4; p++)
#pragma unroll
        for (int q = 0; q < 5; q++) acc2[p][q] = 0ULL;

    float4 xf[4];
    float  vf[3];

    auto fetch = [&](int kb) {
        const int kbase = kb * 16;
#pragma unroll
        for (int r = 0; r < 4; r++) {
            int idx4 = t + 256 * r;                 // 1024 float4 = 16k x 64n4
            int kk = idx4 >> 6, n4 = idx4 & 63;
            xf[r] = *(const float4*)&x[(size_t)(kbase + kk) * NK + n0 + n4 * 4];
        }
#pragma unroll
        for (int r = 0; r < 3; r++) {
            int idx = t + 256 * r;                  // 640 = 16k x 40m
            if (idx < 640) {
                int kk = idx / 40, col = idx - kk * 40;
                vf[r] = g_v[(kbase + kk) * NJD + m0 + col];
            }
        }
    };
    auto sts = [&](int buf) {
#pragma unroll
        for (int r = 0; r < 4; r++) {
            int idx4 = t + 256 * r;
            int kk = idx4 >> 6, n4 = idx4 & 63;
            *(float4*)&Xs[buf][kk][n4 * 4] = xf[r];
        }
#pragma unroll
        for (int r = 0; r < 3; r++) {
            int idx = t + 256 * r;
            if (idx < 640) {
                int kk = idx / 40, col = idx - kk * 40;
                *(float2*)&Vs[buf][kk][col * 2] = make_float2(vf[r], vf[r]);
            }
        }
    };

    fetch(0);
    sts(0);
    __syncthreads();

    for (int kb = 0; kb < 16; kb++) {
        const int buf = kb & 1;
        if (kb < 15) fetch(kb + 1);
#pragma unroll
        for (int kk = 0; kk < 16; kk++) {
            const float* xrow = &Xs[buf][kk][ty * 8];
            ulonglong2 x01 = *(const ulonglong2*)xrow;
            ulonglong2 x23 = *(const ulonglong2*)(xrow + 4);
#pragma unroll
            for (int q = 0; q < 5; q++) {
                unsigned long long vv =
                    *(const unsigned long long*)&Vs[buf][kk][(tx * 5 + q) * 2];
                FMA_F32X2(acc2[0][q], x01.x, vv);
                FMA_F32X2(acc2[1][q], x01.y, vv);
                FMA_F32X2(acc2[2][q], x23.x, vv);
                FMA_F32X2(acc2[3][q], x23.y, vv);
            }
        }
        if (kb < 15) {
            sts(buf ^ 1);
            __syncthreads();
        }
    }

    // Store: thread owns m = m0+tx*5+q, n = n0+ty*8 .. +7  (two float4s each)
#pragma unroll
    for (int q = 0; q < 5; q++) {
        const int m = m0 + tx * 5 + q;
        unsigned l0, h0, l1, h1, l2, h2, l3, h3;
        UNPACK2(l0, h0, acc2[0][q]);
        UNPACK2(l1, h1, acc2[1][q]);
        UNPACK2(l2, h2, acc2[2][q]);
        UNPACK2(l3, h3, acc2[3][q]);
        float4 o0, o1;
        o0.x = __uint_as_float(l0); o0.y = __uint_as_float(h0);
        o0.z = __uint_as_float(l1); o0.w = __uint_as_float(h1);
        o1.x = __uint_as_float(l2); o1.y = __uint_as_float(h2);
        o1.z = __uint_as_float(l3); o1.w = __uint_as_float(h3);
        float* dst = &g_G[(size_t)m * NK + n0 + ty * 8];
        *(float4*)dst = o0;
        *(float4*)(dst + 4) = o1;
    }
}

// ---------------------------------------------------------------------------
// Kernel 5: uv[i,j] = sum_{m=0..127} WT[j*128+m, i] * G[j*128+m, i]
// Non-atomic single-owner writes.
// ---------------------------------------------------------------------------
__global__ __launch_bounds__(128) void uv_reduce() {
    const int i = blockIdx.x * 128 + threadIdx.x;
    const int j = blockIdx.y;
    const size_t base = (size_t)j * 128 * NI + i;
    float acc = 0.f;
#pragma unroll 8
    for (int m = 0; m < 128; m++) {
        acc = fmaf(g_WT[base + (size_t)m * NI], g_G[base + (size_t)m * NI], acc);
    }
    g_uv[i * NJ + j] = acc;
}

// ---------------------------------------------------------------------------
extern "C" void kernel_launch(void* const* d_in, const int* in_sizes, int n_in,
                              void* d_out, int out_size) {
    const float* x = (const float*)d_in[0];   // (256, 8, 1152)
    const float* W = (const float*)d_in[1];   // (1, 1152, 10, 16, 8)
    float* out = (float*)d_out;               // (256, 10, 16, 1)

    prep_kernel<<<dim3(36, 40), dim3(32, 8)>>>(W);

    for (int it = 0; it < 3; it++) {
        softmax_kernel<<<NJ, 128>>>(it == 0 ? 1 : 0);
        s_gemm<<<dim3(4, 36), 256>>>(x);
        squash_kernel<<<16, 256>>>(it == 2 ? out : nullptr);
        if (it < 2) {
            g_gemm<<<dim3(36, 4), 256>>>(x);
            uv_reduce<<<dim3(9, NJ), 128>>>();
        }
    }
}